// round 1
// baseline (speedup 1.0000x reference)
#include <cuda_runtime.h>
#include <cuda_bf16.h>
#include <cstdint>

// Problem: out[i][j] = -sqrt(max(||f_i||^2 + ||f_j||^2 - 2 f_i.f_j, 0))
// f: [8192, 512] fp32.  Strategy: convert f to bf16 once, exact fp32 row norms,
// bf16 tensor-core syrk (mma.sync m16n8k16) with fused epilogue.
// Diagonal forced to exactly 0 (mathematically exact).

#define NROWS 8192
#define DDIM  512

#define BM 128
#define BN 128
#define BK 32
#define LDSZ 40   // BK + 8 bf16 pad -> 80B row stride, conflict-free ldmatrix

__device__ __nv_bfloat16 g_fb[NROWS * DDIM];
__device__ float g_norms[NROWS];

// ---------------------------------------------------------------------------
// Prep: fp32 -> bf16 copy + exact fp32 squared row norms. One block per row.
// ---------------------------------------------------------------------------
__global__ void prep_kernel(const float* __restrict__ f) {
    const int row = blockIdx.x;
    const float* src = f + (size_t)row * DDIM;
    float s = 0.f;
#pragma unroll
    for (int i = threadIdx.x; i < DDIM; i += 256) {
        float v = src[i];
        s += v * v;
        g_fb[(size_t)row * DDIM + i] = __float2bfloat16(v);
    }
    // block reduction
    __shared__ float red[8];
#pragma unroll
    for (int o = 16; o; o >>= 1) s += __shfl_xor_sync(0xffffffffu, s, o);
    if ((threadIdx.x & 31) == 0) red[threadIdx.x >> 5] = s;
    __syncthreads();
    if (threadIdx.x < 8) {
        s = red[threadIdx.x];
#pragma unroll
        for (int o = 4; o; o >>= 1) s += __shfl_xor_sync(0xffu, s, o);
        if (threadIdx.x == 0) g_norms[row] = s;
    }
}

// ---------------------------------------------------------------------------
// GEMM + epilogue. CTA tile 128x128, K-tile 32, 8 warps (2x4), warp tile 64x32.
// Both operands are rows of the same matrix (K-contiguous) -> mma row.col with
// plain (non-trans) ldmatrix on both sides.
// ---------------------------------------------------------------------------
__global__ __launch_bounds__(256, 2)
void gemm_kernel(float* __restrict__ out) {
    __shared__ __nv_bfloat16 As[2][BM][LDSZ];
    __shared__ __nv_bfloat16 Bs[2][BN][LDSZ];

    const int tid  = threadIdx.x;
    const int lane = tid & 31;
    const int warp = tid >> 5;
    const int wm = warp >> 2;  // 0..1
    const int wn = warp & 3;   // 0..3

    const int rowA0 = blockIdx.y * BM;
    const int rowB0 = blockIdx.x * BN;

    float acc[4][4][4];
#pragma unroll
    for (int i = 0; i < 4; i++)
#pragma unroll
        for (int j = 0; j < 4; j++)
#pragma unroll
            for (int r = 0; r < 4; r++) acc[i][j][r] = 0.f;

    // cp.async issue of one K-tile into buffer buf_
#define ISSUE_TILE(kt_, buf_)                                                        \
    do {                                                                             \
        const int k0_ = (kt_) * BK;                                                  \
        _Pragma("unroll")                                                            \
        for (int i_ = 0; i_ < 2; i_++) {                                             \
            int idx_ = tid + i_ * 256;                                               \
            int r_   = idx_ >> 2;                                                    \
            int c_   = (idx_ & 3) << 3;                                              \
            uint32_t sa_ = (uint32_t)__cvta_generic_to_shared(&As[buf_][r_][c_]);    \
            uint32_t sb_ = (uint32_t)__cvta_generic_to_shared(&Bs[buf_][r_][c_]);    \
            const __nv_bfloat16* ga_ = g_fb + (size_t)(rowA0 + r_) * DDIM + k0_ + c_;\
            const __nv_bfloat16* gb_ = g_fb + (size_t)(rowB0 + r_) * DDIM + k0_ + c_;\
            asm volatile("cp.async.cg.shared.global [%0], [%1], 16;\n"               \
                         :: "r"(sa_), "l"(ga_));                                     \
            asm volatile("cp.async.cg.shared.global [%0], [%1], 16;\n"               \
                         :: "r"(sb_), "l"(gb_));                                     \
        }                                                                            \
        asm volatile("cp.async.commit_group;\n");                                    \
    } while (0)

    const int NK = DDIM / BK;  // 16

    ISSUE_TILE(0, 0);
    int buf = 0;

    for (int kt = 0; kt < NK; kt++) {
        if (kt + 1 < NK) {
            ISSUE_TILE(kt + 1, buf ^ 1);
            asm volatile("cp.async.wait_group 1;\n");
        } else {
            asm volatile("cp.async.wait_group 0;\n");
        }
        __syncthreads();

#pragma unroll
        for (int ks = 0; ks < 2; ks++) {  // two k16 steps per BK=32
            uint32_t a[4][4];
            uint32_t b[4][2];
            // A fragments: 4 m-tiles of 16 rows
#pragma unroll
            for (int mt = 0; mt < 4; mt++) {
                int row = wm * 64 + mt * 16 + (lane & 7) + ((lane >> 3) & 1) * 8;
                int kk  = ks * 16 + (lane >> 4) * 8;
                uint32_t addr = (uint32_t)__cvta_generic_to_shared(&As[buf][row][kk]);
                asm volatile(
                    "ldmatrix.sync.aligned.m8n8.x4.shared.b16 {%0,%1,%2,%3}, [%4];\n"
                    : "=r"(a[mt][0]), "=r"(a[mt][1]), "=r"(a[mt][2]), "=r"(a[mt][3])
                    : "r"(addr));
            }
            // B fragments: 4 n-tiles of 8 rows, 2 per ldmatrix.x4
#pragma unroll
            for (int p = 0; p < 2; p++) {
                int row = wn * 32 + p * 16 + (lane & 7) + (lane >> 4) * 8;
                int kk  = ks * 16 + ((lane >> 3) & 1) * 8;
                uint32_t addr = (uint32_t)__cvta_generic_to_shared(&Bs[buf][row][kk]);
                asm volatile(
                    "ldmatrix.sync.aligned.m8n8.x4.shared.b16 {%0,%1,%2,%3}, [%4];\n"
                    : "=r"(b[2 * p][0]), "=r"(b[2 * p][1]),
                      "=r"(b[2 * p + 1][0]), "=r"(b[2 * p + 1][1])
                    : "r"(addr));
            }
            // 16 MMAs
#pragma unroll
            for (int mt = 0; mt < 4; mt++) {
#pragma unroll
                for (int nt = 0; nt < 4; nt++) {
                    asm volatile(
                        "mma.sync.aligned.m16n8k16.row.col.f32.bf16.bf16.f32 "
                        "{%0,%1,%2,%3}, {%4,%5,%6,%7}, {%8,%9}, {%0,%1,%2,%3};\n"
                        : "+f"(acc[mt][nt][0]), "+f"(acc[mt][nt][1]),
                          "+f"(acc[mt][nt][2]), "+f"(acc[mt][nt][3])
                        : "r"(a[mt][0]), "r"(a[mt][1]), "r"(a[mt][2]), "r"(a[mt][3]),
                          "r"(b[nt][0]), "r"(b[nt][1]));
                }
            }
        }
        __syncthreads();
        buf ^= 1;
    }

    // Epilogue: out = -sqrt(max(na + nb - 2g, 0)), diagonal forced to 0.
#pragma unroll
    for (int mt = 0; mt < 4; mt++) {
        int r0 = rowA0 + wm * 64 + mt * 16 + (lane >> 2);
        int r1 = r0 + 8;
        float na0 = g_norms[r0];
        float na1 = g_norms[r1];
#pragma unroll
        for (int nt = 0; nt < 4; nt++) {
            int c0 = rowB0 + wn * 32 + nt * 8 + 2 * (lane & 3);
            int c1 = c0 + 1;
            float nb0 = g_norms[c0];
            float nb1 = g_norms[c1];

            float d00 = fmaxf(na0 + nb0 - 2.f * acc[mt][nt][0], 0.f);
            float d01 = fmaxf(na0 + nb1 - 2.f * acc[mt][nt][1], 0.f);
            float d10 = fmaxf(na1 + nb0 - 2.f * acc[mt][nt][2], 0.f);
            float d11 = fmaxf(na1 + nb1 - 2.f * acc[mt][nt][3], 0.f);

            float v00 = (r0 == c0) ? 0.f : -sqrtf(d00);
            float v01 = (r0 == c1) ? 0.f : -sqrtf(d01);
            float v10 = (r1 == c0) ? 0.f : -sqrtf(d10);
            float v11 = (r1 == c1) ? 0.f : -sqrtf(d11);

            *(float2*)&out[(size_t)r0 * NROWS + c0] = make_float2(v00, v01);
            *(float2*)&out[(size_t)r1 * NROWS + c0] = make_float2(v10, v11);
        }
    }
#undef ISSUE_TILE
}

// ---------------------------------------------------------------------------
extern "C" void kernel_launch(void* const* d_in, const int* in_sizes, int n_in,
                              void* d_out, int out_size) {
    const float* f = (const float*)d_in[0];
    float* out = (float*)d_out;
    (void)in_sizes; (void)n_in; (void)out_size;

    prep_kernel<<<NROWS, 256>>>(f);
    dim3 grid(NROWS / BN, NROWS / BM);
    gemm_kernel<<<grid, 256>>>(out);
}

// round 2
// speedup vs baseline: 1.0004x; 1.0004x over previous
#include <cuda_runtime.h>
#include <cuda_bf16.h>
#include <cstdint>

// Problem: out[i][j] = -sqrt(max(||f_i||^2 + ||f_j||^2 - 2 f_i.f_j, 0))
// f: [8192, 512] fp32.  Strategy: convert f to bf16 once, exact fp32 row norms,
// bf16 tensor-core syrk (mma.sync m16n8k16) with fused epilogue.
// Diagonal forced to exactly 0 (mathematically exact).

#define NROWS 8192
#define DDIM  512

#define BM 128
#define BN 128
#define BK 32
#define LDSZ 40   // BK + 8 bf16 pad -> 80B row stride, conflict-free ldmatrix

__device__ __nv_bfloat16 g_fb[NROWS * DDIM];
__device__ float g_norms[NROWS];

// ---------------------------------------------------------------------------
// Prep: fp32 -> bf16 copy + exact fp32 squared row norms. One block per row.
// ---------------------------------------------------------------------------
__global__ void prep_kernel(const float* __restrict__ f) {
    const int row = blockIdx.x;
    const float* src = f + (size_t)row * DDIM;
    float s = 0.f;
#pragma unroll
    for (int i = threadIdx.x; i < DDIM; i += 256) {
        float v = src[i];
        s += v * v;
        g_fb[(size_t)row * DDIM + i] = __float2bfloat16(v);
    }
    // block reduction
    __shared__ float red[8];
#pragma unroll
    for (int o = 16; o; o >>= 1) s += __shfl_xor_sync(0xffffffffu, s, o);
    if ((threadIdx.x & 31) == 0) red[threadIdx.x >> 5] = s;
    __syncthreads();
    if (threadIdx.x < 8) {
        s = red[threadIdx.x];
#pragma unroll
        for (int o = 4; o; o >>= 1) s += __shfl_xor_sync(0xffu, s, o);
        if (threadIdx.x == 0) g_norms[row] = s;
    }
}

// ---------------------------------------------------------------------------
// GEMM + epilogue. CTA tile 128x128, K-tile 32, 8 warps (2x4), warp tile 64x32.
// Both operands are rows of the same matrix (K-contiguous) -> mma row.col with
// plain (non-trans) ldmatrix on both sides.
// ---------------------------------------------------------------------------
__global__ __launch_bounds__(256, 2)
void gemm_kernel(float* __restrict__ out) {
    __shared__ __nv_bfloat16 As[2][BM][LDSZ];
    __shared__ __nv_bfloat16 Bs[2][BN][LDSZ];

    const int tid  = threadIdx.x;
    const int lane = tid & 31;
    const int warp = tid >> 5;
    const int wm = warp >> 2;  // 0..1
    const int wn = warp & 3;   // 0..3

    const int rowA0 = blockIdx.y * BM;
    const int rowB0 = blockIdx.x * BN;

    float acc[4][4][4];
#pragma unroll
    for (int i = 0; i < 4; i++)
#pragma unroll
        for (int j = 0; j < 4; j++)
#pragma unroll
            for (int r = 0; r < 4; r++) acc[i][j][r] = 0.f;

    // cp.async issue of one K-tile into buffer buf_
#define ISSUE_TILE(kt_, buf_)                                                        \
    do {                                                                             \
        const int k0_ = (kt_) * BK;                                                  \
        _Pragma("unroll")                                                            \
        for (int i_ = 0; i_ < 2; i_++) {                                             \
            int idx_ = tid + i_ * 256;                                               \
            int r_   = idx_ >> 2;                                                    \
            int c_   = (idx_ & 3) << 3;                                              \
            uint32_t sa_ = (uint32_t)__cvta_generic_to_shared(&As[buf_][r_][c_]);    \
            uint32_t sb_ = (uint32_t)__cvta_generic_to_shared(&Bs[buf_][r_][c_]);    \
            const __nv_bfloat16* ga_ = g_fb + (size_t)(rowA0 + r_) * DDIM + k0_ + c_;\
            const __nv_bfloat16* gb_ = g_fb + (size_t)(rowB0 + r_) * DDIM + k0_ + c_;\
            asm volatile("cp.async.cg.shared.global [%0], [%1], 16;\n"               \
                         :: "r"(sa_), "l"(ga_));                                     \
            asm volatile("cp.async.cg.shared.global [%0], [%1], 16;\n"               \
                         :: "r"(sb_), "l"(gb_));                                     \
        }                                                                            \
        asm volatile("cp.async.commit_group;\n");                                    \
    } while (0)

    const int NK = DDIM / BK;  // 16

    ISSUE_TILE(0, 0);
    int buf = 0;

    for (int kt = 0; kt < NK; kt++) {
        if (kt + 1 < NK) {
            ISSUE_TILE(kt + 1, buf ^ 1);
            asm volatile("cp.async.wait_group 1;\n");
        } else {
            asm volatile("cp.async.wait_group 0;\n");
        }
        __syncthreads();

#pragma unroll
        for (int ks = 0; ks < 2; ks++) {  // two k16 steps per BK=32
            uint32_t a[4][4];
            uint32_t b[4][2];
            // A fragments: 4 m-tiles of 16 rows
#pragma unroll
            for (int mt = 0; mt < 4; mt++) {
                int row = wm * 64 + mt * 16 + (lane & 7) + ((lane >> 3) & 1) * 8;
                int kk  = ks * 16 + (lane >> 4) * 8;
                uint32_t addr = (uint32_t)__cvta_generic_to_shared(&As[buf][row][kk]);
                asm volatile(
                    "ldmatrix.sync.aligned.m8n8.x4.shared.b16 {%0,%1,%2,%3}, [%4];\n"
                    : "=r"(a[mt][0]), "=r"(a[mt][1]), "=r"(a[mt][2]), "=r"(a[mt][3])
                    : "r"(addr));
            }
            // B fragments: 4 n-tiles of 8 rows, 2 per ldmatrix.x4
#pragma unroll
            for (int p = 0; p < 2; p++) {
                int row = wn * 32 + p * 16 + (lane & 7) + (lane >> 4) * 8;
                int kk  = ks * 16 + ((lane >> 3) & 1) * 8;
                uint32_t addr = (uint32_t)__cvta_generic_to_shared(&Bs[buf][row][kk]);
                asm volatile(
                    "ldmatrix.sync.aligned.m8n8.x4.shared.b16 {%0,%1,%2,%3}, [%4];\n"
                    : "=r"(b[2 * p][0]), "=r"(b[2 * p][1]),
                      "=r"(b[2 * p + 1][0]), "=r"(b[2 * p + 1][1])
                    : "r"(addr));
            }
            // 16 MMAs
#pragma unroll
            for (int mt = 0; mt < 4; mt++) {
#pragma unroll
                for (int nt = 0; nt < 4; nt++) {
                    asm volatile(
                        "mma.sync.aligned.m16n8k16.row.col.f32.bf16.bf16.f32 "
                        "{%0,%1,%2,%3}, {%4,%5,%6,%7}, {%8,%9}, {%0,%1,%2,%3};\n"
                        : "+f"(acc[mt][nt][0]), "+f"(acc[mt][nt][1]),
                          "+f"(acc[mt][nt][2]), "+f"(acc[mt][nt][3])
                        : "r"(a[mt][0]), "r"(a[mt][1]), "r"(a[mt][2]), "r"(a[mt][3]),
                          "r"(b[nt][0]), "r"(b[nt][1]));
                }
            }
        }
        __syncthreads();
        buf ^= 1;
    }

    // Epilogue: out = -sqrt(max(na + nb - 2g, 0)), diagonal forced to 0.
#pragma unroll
    for (int mt = 0; mt < 4; mt++) {
        int r0 = rowA0 + wm * 64 + mt * 16 + (lane >> 2);
        int r1 = r0 + 8;
        float na0 = g_norms[r0];
        float na1 = g_norms[r1];
#pragma unroll
        for (int nt = 0; nt < 4; nt++) {
            int c0 = rowB0 + wn * 32 + nt * 8 + 2 * (lane & 3);
            int c1 = c0 + 1;
            float nb0 = g_norms[c0];
            float nb1 = g_norms[c1];

            float d00 = fmaxf(na0 + nb0 - 2.f * acc[mt][nt][0], 0.f);
            float d01 = fmaxf(na0 + nb1 - 2.f * acc[mt][nt][1], 0.f);
            float d10 = fmaxf(na1 + nb0 - 2.f * acc[mt][nt][2], 0.f);
            float d11 = fmaxf(na1 + nb1 - 2.f * acc[mt][nt][3], 0.f);

            float v00 = (r0 == c0) ? 0.f : -sqrtf(d00);
            float v01 = (r0 == c1) ? 0.f : -sqrtf(d01);
            float v10 = (r1 == c0) ? 0.f : -sqrtf(d10);
            float v11 = (r1 == c1) ? 0.f : -sqrtf(d11);

            *(float2*)&out[(size_t)r0 * NROWS + c0] = make_float2(v00, v01);
            *(float2*)&out[(size_t)r1 * NROWS + c0] = make_float2(v10, v11);
        }
    }
#undef ISSUE_TILE
}

// ---------------------------------------------------------------------------
extern "C" void kernel_launch(void* const* d_in, const int* in_sizes, int n_in,
                              void* d_out, int out_size) {
    const float* f = (const float*)d_in[0];
    float* out = (float*)d_out;
    (void)in_sizes; (void)n_in; (void)out_size;

    prep_kernel<<<NROWS, 256>>>(f);
    dim3 grid(NROWS / BN, NROWS / BM);
    gemm_kernel<<<grid, 256>>>(out);
}